// round 1
// baseline (speedup 1.0000x reference)
#include <cuda_runtime.h>

#define C 128
#define NUM_ITERS 10

// Tiny scratch state (allowed: __device__ globals, no allocation).
__device__ __align__(16) float g_v[2][C];   // ping-pong col-scaling vectors
__device__ float g_b[C];                    // target column marginals b = ratios * total_num
__device__ float g_colsum[C];               // global column-sum accumulator

// ---------------------------------------------------------------------------
// init: b = ratios * total_num ; v0 = 1 ; colsum = 0
// ---------------------------------------------------------------------------
__global__ void init_k(const float* __restrict__ ratios,
                       const int* __restrict__ total_num) {
    int j = threadIdx.x;
    float tn = (float)(*total_num);
    g_b[j] = ratios[j] * tn;
    g_v[0][j] = 1.0f;
    g_v[1][j] = 1.0f;
    g_colsum[j] = 0.0f;
}

// ---------------------------------------------------------------------------
// One Sinkhorn iteration pass (read-only over S):
//   per row i: u_i = 1 / sum_j exp(S_ij) * v_in[j]
//   accumulate colsum[j] += u_i * exp(S_ij)
// One warp per row; lane l owns columns 4l..4l+3 via a float4 load.
// ---------------------------------------------------------------------------
__global__ void __launch_bounds__(256)
iter_k(const float4* __restrict__ S4, int N, int parity_in) {
    const int lane = threadIdx.x & 31;
    const int warps_per_block = blockDim.x >> 5;
    const int gwarp = blockIdx.x * warps_per_block + (threadIdx.x >> 5);
    const int nwarps = gridDim.x * warps_per_block;

    // v_in held in registers (same 4 columns for every row this lane touches)
    float4 v = reinterpret_cast<const float4*>(g_v[parity_in])[lane];

    float c0 = 0.f, c1 = 0.f, c2 = 0.f, c3 = 0.f;

    for (int row = gwarp; row < N; row += nwarps) {
        float4 s = S4[(size_t)row * (C / 4) + lane];
        float e0 = __expf(s.x);
        float e1 = __expf(s.y);
        float e2 = __expf(s.z);
        float e3 = __expf(s.w);
        float p = fmaf(e0, v.x, fmaf(e1, v.y, fmaf(e2, v.z, e3 * v.w)));
        #pragma unroll
        for (int o = 16; o; o >>= 1)
            p += __shfl_xor_sync(0xffffffffu, p, o);
        float u = 1.0f / p;
        c0 = fmaf(u, e0, c0);
        c1 = fmaf(u, e1, c1);
        c2 = fmaf(u, e2, c2);
        c3 = fmaf(u, e3, c3);
    }

    // Block-local reduction of column partials, then one atomicAdd per column.
    __shared__ float scol[C];
    if (threadIdx.x < C) scol[threadIdx.x] = 0.0f;
    __syncthreads();
    int col = lane * 4;
    atomicAdd(&scol[col + 0], c0);
    atomicAdd(&scol[col + 1], c1);
    atomicAdd(&scol[col + 2], c2);
    atomicAdd(&scol[col + 3], c3);
    __syncthreads();
    if (threadIdx.x < C)
        atomicAdd(&g_colsum[threadIdx.x], scol[threadIdx.x]);
}

// ---------------------------------------------------------------------------
// v_out[j] = b[j] / colsum[j] ; reset colsum for next iteration
// ---------------------------------------------------------------------------
__global__ void vnorm_k(int parity_out) {
    int j = threadIdx.x;
    g_v[parity_out][j] = g_b[j] / g_colsum[j];
    g_colsum[j] = 0.0f;
}

// ---------------------------------------------------------------------------
// Final pass: P_ij = u_i * exp(S_ij) * v10[j], u_i = 1/sum_j exp(S_ij)*v9[j]
// v9 lives in g_v[1], v10 in g_v[0] (after 10 iterations).
// ---------------------------------------------------------------------------
__global__ void __launch_bounds__(256)
final_k(const float4* __restrict__ S4, float4* __restrict__ out, int N) {
    const int lane = threadIdx.x & 31;
    const int warps_per_block = blockDim.x >> 5;
    const int gwarp = blockIdx.x * warps_per_block + (threadIdx.x >> 5);
    const int nwarps = gridDim.x * warps_per_block;

    float4 v9  = reinterpret_cast<const float4*>(g_v[1])[lane];
    float4 v10 = reinterpret_cast<const float4*>(g_v[0])[lane];

    for (int row = gwarp; row < N; row += nwarps) {
        float4 s = S4[(size_t)row * (C / 4) + lane];
        float e0 = __expf(s.x);
        float e1 = __expf(s.y);
        float e2 = __expf(s.z);
        float e3 = __expf(s.w);
        float p = fmaf(e0, v9.x, fmaf(e1, v9.y, fmaf(e2, v9.z, e3 * v9.w)));
        #pragma unroll
        for (int o = 16; o; o >>= 1)
            p += __shfl_xor_sync(0xffffffffu, p, o);
        float u = 1.0f / p;
        float4 o4;
        o4.x = u * e0 * v10.x;
        o4.y = u * e1 * v10.y;
        o4.z = u * e2 * v10.z;
        o4.w = u * e3 * v10.w;
        out[(size_t)row * (C / 4) + lane] = o4;
    }
}

// ---------------------------------------------------------------------------
// Inputs (metadata order): 0 features[4096,512] f32 (unused),
// 1 text_features[128,512] f32 (unused), 2 sim_matrix_whole[500000,128] f32,
// 3 ratios[128] f32, 4 targets[4096] i32 (unused), 5 total_num scalar i32.
// Output: P [500000,128] f32.
// ---------------------------------------------------------------------------
extern "C" void kernel_launch(void* const* d_in, const int* in_sizes, int n_in,
                              void* d_out, int out_size) {
    const float* S        = (const float*)d_in[2];
    const float* ratios   = (const float*)d_in[3];
    const int*   totalnum = (const int*)d_in[5];
    const int N = in_sizes[2] / C;

    const int GRID = 1184;   // 148 SMs * 8 blocks, grid-stride
    const int BLK  = 256;

    init_k<<<1, C>>>(ratios, totalnum);
    for (int t = 1; t <= NUM_ITERS; ++t) {
        iter_k<<<GRID, BLK>>>((const float4*)S, N, (t - 1) & 1);
        vnorm_k<<<1, C>>>(t & 1);
    }
    final_k<<<GRID, BLK>>>((const float4*)S, (float4*)d_out, N);
}